// round 1
// baseline (speedup 1.0000x reference)
#include <cuda_runtime.h>
#include <cuda_bf16.h>
#include <math.h>

// Problem constants
#define B_   2
#define S_   2048
#define DM_  1024
#define H_   16
#define KVH_ 4
#define NG_  4          // H_/KVH_
#define DH_  64
#define WINDOW_ 256
#define NGLOBAL_ 4
#define ATTN_SCALE_ 0.125f   // 1/sqrt(64)

// Scratch (static device allocations; no cudaMalloc allowed)
__device__ float g_q[(size_t)B_ * H_ * S_ * DH_];     // [b,h,s,d]
__device__ float g_k[(size_t)B_ * KVH_ * S_ * DH_];   // [b,kvh,s,d]
__device__ float g_v[(size_t)B_ * KVH_ * S_ * DH_];   // [b,kvh,s,d]
__device__ float g_ctx[(size_t)B_ * S_ * H_ * DH_];   // [b,s,h,d] == row-major [4096,1024]

// ---------------------------------------------------------------------------
// SGEMM: C = A[M,K] @ W[K,N], fp32. BM=BN=64, BK=16, 256 threads, 4x4 microtile.
// mode 0: scatter to [b, h, s, d] with h = n/64, b = m/S_, s = m%S_
// mode 1: plain row-major C[m*N + n]
// All dims divide tile sizes exactly for this problem.
// ---------------------------------------------------------------------------
__global__ void sgemm_kernel(const float* __restrict__ A, const float* __restrict__ W,
                             float* __restrict__ C, int M, int N, int K, int mode)
{
    __shared__ float As[16][64];
    __shared__ float Bs[16][64];

    const int tid = threadIdx.x;
    const int tx = tid & 15;         // 0..15 -> n
    const int ty = tid >> 4;         // 0..15 -> m
    const int m0 = blockIdx.y * 64;
    const int n0 = blockIdx.x * 64;

    float acc[4][4];
#pragma unroll
    for (int i = 0; i < 4; ++i)
#pragma unroll
        for (int j = 0; j < 4; ++j) acc[i][j] = 0.f;

    for (int k0 = 0; k0 < K; k0 += 16) {
        // A tile: 64 rows x 16 cols. One float4 per thread.
        {
            int r  = tid >> 2;
            int c4 = (tid & 3) * 4;
            float4 v = *reinterpret_cast<const float4*>(&A[(size_t)(m0 + r) * K + k0 + c4]);
            As[c4 + 0][r] = v.x; As[c4 + 1][r] = v.y;
            As[c4 + 2][r] = v.z; As[c4 + 3][r] = v.w;
        }
        // B tile: 16 rows x 64 cols. One float4 per thread.
        {
            int r  = tid >> 4;
            int c4 = (tid & 15) * 4;
            float4 v = *reinterpret_cast<const float4*>(&W[(size_t)(k0 + r) * N + n0 + c4]);
            *reinterpret_cast<float4*>(&Bs[r][c4]) = v;
        }
        __syncthreads();

#pragma unroll
        for (int kk = 0; kk < 16; ++kk) {
            float a[4], b[4];
#pragma unroll
            for (int i = 0; i < 4; ++i) a[i] = As[kk][ty * 4 + i];
#pragma unroll
            for (int j = 0; j < 4; ++j) b[j] = Bs[kk][tx * 4 + j];
#pragma unroll
            for (int i = 0; i < 4; ++i)
#pragma unroll
                for (int j = 0; j < 4; ++j)
                    acc[i][j] += a[i] * b[j];
        }
        __syncthreads();
    }

    if (mode == 1) {
#pragma unroll
        for (int i = 0; i < 4; ++i) {
            int m = m0 + ty * 4 + i;
#pragma unroll
            for (int j = 0; j < 4; ++j) {
                int n = n0 + tx * 4 + j;
                C[(size_t)m * N + n] = acc[i][j];
            }
        }
    } else {
        int nheads = N >> 6;   // N / 64
#pragma unroll
        for (int i = 0; i < 4; ++i) {
            int m = m0 + ty * 4 + i;
            int b = m / S_, s = m % S_;
#pragma unroll
            for (int j = 0; j < 4; ++j) {
                int n = n0 + tx * 4 + j;
                int h = n >> 6, d = n & 63;
                C[((((size_t)b * nheads + h) * S_) + s) * DH_ + d] = acc[i][j];
            }
        }
    }
}

// ---------------------------------------------------------------------------
// L2-normalize (over D=64) then RoPE, in-place. One warp per (b,h,s) row.
// ---------------------------------------------------------------------------
__global__ void norm_rope_kernel(float* __restrict__ t, const float* __restrict__ cosb,
                                 const float* __restrict__ sinb, int nrows)
{
    int gwarp = (blockIdx.x * blockDim.x + threadIdx.x) >> 5;
    int lane  = threadIdx.x & 31;
    if (gwarp >= nrows) return;
    int s = gwarp % S_;
    float* row = t + (size_t)gwarp * DH_;

    float e1 = row[lane];
    float e2 = row[lane + 32];
    float ss = e1 * e1 + e2 * e2;
#pragma unroll
    for (int o = 16; o; o >>= 1) ss += __shfl_xor_sync(0xffffffffu, ss, o);
    float inv = 1.0f / (sqrtf(ss) + 1e-8f);
    e1 *= inv; e2 *= inv;

    float c  = cosb[s * 32 + lane];
    float sn = sinb[s * 32 + lane];
    row[lane]      = e1 * c  - e2 * sn;
    row[lane + 32] = e1 * sn + e2 * c;
}

// ---------------------------------------------------------------------------
// Attention: block = 8 consecutive queries of one (b,h); 8 warps, 1 query/warp.
// K/V staged in shared 64-key chunks. Sliding window 256 + 4 global keys.
// Softcap 15*tanh(s/15) applied pre-mask (matches reference). Online softmax.
// ---------------------------------------------------------------------------
__global__ void attn_kernel(const float* __restrict__ Q, const float* __restrict__ Kb,
                            const float* __restrict__ Vb, float* __restrict__ ctx)
{
    __shared__ float Ks[64][65];
    __shared__ float Vs[64][65];
    __shared__ float Qs[8][64];

    const int lane = threadIdx.x & 31;
    const int w    = threadIdx.x >> 5;
    const int b    = blockIdx.z;
    const int h    = blockIdx.y;
    const int q0   = blockIdx.x * 8;
    const int q    = q0 + w;
    const int kvh  = h / NG_;

    const float* qrow = Q + ((((size_t)b * H_ + h) * S_) + q) * DH_;
    Qs[w][lane]      = qrow[lane];
    Qs[w][lane + 32] = qrow[lane + 32];

    const float* Kbase = Kb + (((size_t)b * KVH_ + kvh) * S_) * DH_;
    const float* Vbase = Vb + (((size_t)b * KVH_ + kvh) * S_) * DH_;

    float m_run = -INFINITY, l_run = 0.f, o0 = 0.f, o1 = 0.f;

    int q_lo = q0 - (WINDOW_ - 1); if (q_lo < 0) q_lo = 0;
    const int c_lo  = q_lo >> 6;
    const int c_hi  = (q0 + 7) >> 6;
    const int extra = (c_lo > 0) ? 1 : 0;
    const int nch   = c_hi - c_lo + 1 + extra;

    for (int it = 0; it < nch; ++it) {
        int c = extra ? (it == 0 ? 0 : c_lo + it - 1) : (c_lo + it);

        __syncthreads();
        // cooperative load of 64 keys + values (4096 floats each)
        for (int i = threadIdx.x; i < 1024; i += 256) {
            int r  = i >> 4;
            int c4 = (i & 15) * 4;
            const float* kp = &Kbase[((size_t)(c * 64 + r)) * DH_ + c4];
            const float* vp = &Vbase[((size_t)(c * 64 + r)) * DH_ + c4];
            float4 kv = *reinterpret_cast<const float4*>(kp);
            float4 vv = *reinterpret_cast<const float4*>(vp);
            Ks[r][c4] = kv.x; Ks[r][c4 + 1] = kv.y; Ks[r][c4 + 2] = kv.z; Ks[r][c4 + 3] = kv.w;
            Vs[r][c4] = vv.x; Vs[r][c4 + 1] = vv.y; Vs[r][c4 + 2] = vv.z; Vs[r][c4 + 3] = vv.w;
        }
        __syncthreads();

        const int j0 = lane, j1 = lane + 32;
        const int k0a = c * 64 + j0, k1a = c * 64 + j1;

        float s0 = 0.f, s1 = 0.f;
#pragma unroll
        for (int d = 0; d < 64; ++d) {
            float qd = Qs[w][d];
            s0 += qd * Ks[j0][d];
            s1 += qd * Ks[j1][d];
        }
        s0 *= ATTN_SCALE_;  s1 *= ATTN_SCALE_;
        s0 = 15.0f * tanhf(s0 * (1.0f / 15.0f));
        s1 = 15.0f * tanhf(s1 * (1.0f / 15.0f));

        bool v0 = (k0a <= q) && ((k0a + WINDOW_ > q) || (k0a < NGLOBAL_));
        bool v1 = (k1a <= q) && ((k1a + WINDOW_ > q) || (k1a < NGLOBAL_));
        if (!v0) s0 = -INFINITY;
        if (!v1) s1 = -INFINITY;

        float cm = fmaxf(s0, s1);
#pragma unroll
        for (int o = 16; o; o >>= 1) cm = fmaxf(cm, __shfl_xor_sync(0xffffffffu, cm, o));

        if (cm != -INFINITY) {
            float m_new = fmaxf(m_run, cm);
            float alpha = __expf(m_run - m_new);
            o0 *= alpha; o1 *= alpha; l_run *= alpha;

            float p0 = __expf(s0 - m_new);
            float p1 = __expf(s1 - m_new);
            float ps = p0 + p1;
#pragma unroll
            for (int o = 16; o; o >>= 1) ps += __shfl_xor_sync(0xffffffffu, ps, o);
            l_run += ps;

#pragma unroll
            for (int j = 0; j < 32; ++j) {
                float wj = __shfl_sync(0xffffffffu, p0, j);
                o0 += wj * Vs[j][lane];
                o1 += wj * Vs[j][lane + 32];
            }
#pragma unroll
            for (int j = 0; j < 32; ++j) {
                float wj = __shfl_sync(0xffffffffu, p1, j);
                o0 += wj * Vs[32 + j][lane];
                o1 += wj * Vs[32 + j][lane + 32];
            }
            m_run = m_new;
        }
    }

    float invl = 1.0f / l_run;
    float* crow = ctx + ((((size_t)b * S_ + q) * H_) + h) * DH_;
    crow[lane]      = o0 * invl;
    crow[lane + 32] = o1 * invl;
}

// ---------------------------------------------------------------------------
// Launch
// ---------------------------------------------------------------------------
extern "C" void kernel_launch(void* const* d_in, const int* in_sizes, int n_in,
                              void* d_out, int out_size)
{
    const float* x    = (const float*)d_in[0];
    const float* cosb = (const float*)d_in[1];
    const float* sinb = (const float*)d_in[2];
    // d_in[3] = mask (pure causal) — computed analytically, unused
    const float* Wq   = (const float*)d_in[4];
    const float* Wk   = (const float*)d_in[5];
    const float* Wv   = (const float*)d_in[6];
    const float* Wo   = (const float*)d_in[7];
    float* out        = (float*)d_out;

    float *qp, *kp, *vp, *cp;
    cudaGetSymbolAddress((void**)&qp, g_q);
    cudaGetSymbolAddress((void**)&kp, g_k);
    cudaGetSymbolAddress((void**)&vp, g_v);
    cudaGetSymbolAddress((void**)&cp, g_ctx);

    const int M = B_ * S_;     // 4096
    dim3 t(256);

    // QKV projections (epilogue scatters to [b,h,s,d])
    sgemm_kernel<<<dim3(16, M / 64), t>>>(x, Wq, qp, M, H_ * DH_,  DM_, 0);
    sgemm_kernel<<<dim3(4,  M / 64), t>>>(x, Wk, kp, M, KVH_ * DH_, DM_, 0);
    sgemm_kernel<<<dim3(4,  M / 64), t>>>(x, Wv, vp, M, KVH_ * DH_, DM_, 0);

    // L2-norm + RoPE (q and k)
    norm_rope_kernel<<<(B_ * H_ * S_)   / 8, t>>>(qp, cosb, sinb, B_ * H_ * S_);
    norm_rope_kernel<<<(B_ * KVH_ * S_) / 8, t>>>(kp, cosb, sinb, B_ * KVH_ * S_);

    // Attention
    attn_kernel<<<dim3(S_ / 8, H_, B_), t>>>(qp, kp, vp, cp);

    // Output projection (row-major into d_out)
    sgemm_kernel<<<dim3(16, M / 64), t>>>(cp, Wo, out, M, DM_, DM_, 1);
}

// round 2
// speedup vs baseline: 1.4804x; 1.4804x over previous
#include <cuda_runtime.h>
#include <cuda_bf16.h>
#include <math.h>
#include <stdint.h>

// Problem constants
#define B_   2
#define S_   2048
#define DM_  1024
#define H_   16
#define KVH_ 4
#define NG_  4          // H_/KVH_
#define DH_  64
#define WINDOW_ 256
#define NGLOBAL_ 4
#define ATTN_SCALE_ 0.125f   // 1/sqrt(64)

// Scratch (static device allocations; no cudaMalloc allowed)
__device__ float g_q[(size_t)B_ * H_ * S_ * DH_];     // [b,h,s,d]
__device__ float g_k[(size_t)B_ * KVH_ * S_ * DH_];   // [b,kvh,s,d]
__device__ float g_v[(size_t)B_ * KVH_ * S_ * DH_];   // [b,kvh,s,d]
__device__ float g_ctx[(size_t)B_ * S_ * H_ * DH_];   // [b,s,h,d] == row-major [4096,1024]

__device__ __forceinline__ float to_tf32(float x) {
    asm("cvt.rna.tf32.f32 %0, %0;" : "+f"(x));
    return x;
}

// ---------------------------------------------------------------------------
// tf32 tensor-core GEMM: C = A[M,K] @ W[K,N], fp32 accumulate.
// BM=128, BN=128, BK=16. 256 threads = 8 warps in 2(M)x4(N); warp tile 64x32.
// mma.sync.aligned.m16n8k8.row.col.f32.tf32.tf32.f32
// mode 0: scatter to [b, h, s, d] with h = n/64, b = m/S_, s = m%S_
// mode 1: plain row-major C[m*N + n]
// M % 128 == 0, N % 128 == 0, K % 16 == 0 for this problem.
// ---------------------------------------------------------------------------
#define BM 128
#define BN 128
#define BK 16

__global__ __launch_bounds__(256) void tf32_gemm(const float* __restrict__ A,
                                                 const float* __restrict__ W,
                                                 float* __restrict__ C,
                                                 int M, int N, int K, int mode)
{
    // A staged [m][k] with pad 20 floats/row (conflict-free frag loads, 16B-aligned STS.128)
    // B staged [k][n] with pad 136 floats/row (conflict-free frag loads)
    __shared__ float As[2][BM][20];
    __shared__ float Bs[2][BK][136];

    const int tid  = threadIdx.x;
    const int wid  = tid >> 5;
    const int lane = tid & 31;
    const int g    = lane >> 2;   // group id 0..7
    const int q    = lane & 3;    // thread-in-group 0..3
    const int m0   = blockIdx.y * BM;
    const int n0   = blockIdx.x * BN;
    const int wm   = (wid >> 2) * 64;   // warp m offset in block
    const int wn   = (wid & 3) * 32;    // warp n offset in block

    float acc[4][4][4];
#pragma unroll
    for (int i = 0; i < 4; ++i)
#pragma unroll
        for (int j = 0; j < 4; ++j)
#pragma unroll
            for (int r = 0; r < 4; ++r) acc[i][j][r] = 0.f;

    float4 ra[2], rb[2];

    const int T = K / BK;

    // ---- prologue: load tile 0 into buffer 0 ----
    {
        const int k0 = 0;
#pragma unroll
        for (int i = 0; i < 2; ++i) {
            int lin = tid * 4 + i * 1024;
            int arr = lin >> 4, acn = lin & 15;         // A tile 128x16
            ra[i] = *reinterpret_cast<const float4*>(&A[(size_t)(m0 + arr) * K + k0 + acn]);
            int brr = lin >> 7, bcn = lin & 127;        // B tile 16x128
            rb[i] = *reinterpret_cast<const float4*>(&W[(size_t)(k0 + brr) * N + n0 + bcn]);
        }
#pragma unroll
        for (int i = 0; i < 2; ++i) {
            int lin = tid * 4 + i * 1024;
            int arr = lin >> 4, acn = lin & 15;
            float4 va = ra[i];
            va.x = to_tf32(va.x); va.y = to_tf32(va.y);
            va.z = to_tf32(va.z); va.w = to_tf32(va.w);
            *reinterpret_cast<float4*>(&As[0][arr][acn]) = va;
            int brr = lin >> 7, bcn = lin & 127;
            float4 vb = rb[i];
            vb.x = to_tf32(vb.x); vb.y = to_tf32(vb.y);
            vb.z = to_tf32(vb.z); vb.w = to_tf32(vb.w);
            *reinterpret_cast<float4*>(&Bs[0][brr][bcn]) = vb;
        }
    }
    __syncthreads();

    int buf = 0;
    for (int t = 0; t < T; ++t) {
        // prefetch next tile into registers
        if (t + 1 < T) {
            const int k0 = (t + 1) * BK;
#pragma unroll
            for (int i = 0; i < 2; ++i) {
                int lin = tid * 4 + i * 1024;
                int arr = lin >> 4, acn = lin & 15;
                ra[i] = *reinterpret_cast<const float4*>(&A[(size_t)(m0 + arr) * K + k0 + acn]);
                int brr = lin >> 7, bcn = lin & 127;
                rb[i] = *reinterpret_cast<const float4*>(&W[(size_t)(k0 + brr) * N + n0 + bcn]);
            }
        }

        // compute on current buffer: 2 k8-steps
#pragma unroll
        for (int kk = 0; kk < 2; ++kk) {
            const int kb = kk * 8;
            uint32_t af[4][4], bf[4][2];
#pragma unroll
            for (int mf = 0; mf < 4; ++mf) {
                const int mrow = wm + mf * 16;
                af[mf][0] = __float_as_uint(As[buf][mrow + g    ][kb + q    ]);
                af[mf][1] = __float_as_uint(As[buf][mrow + g + 8][kb + q    ]);
                af[mf][2] = __float_as_uint(As[buf][mrow + g    ][kb + q + 4]);
                af[mf][3] = __float_as_uint(As[buf][mrow + g + 8][kb + q + 4]);
            }
#pragma unroll
            for (int nf = 0; nf < 4; ++nf) {
                const int ncol = wn + nf * 8 + g;
                bf[nf][0] = __float_as_uint(Bs[buf][kb + q    ][ncol]);
                bf[nf][1] = __float_as_uint(Bs[buf][kb + q + 4][ncol]);
            }
#pragma unroll
            for (int mf = 0; mf < 4; ++mf)
#pragma unroll
                for (int nf = 0; nf < 4; ++nf) {
                    asm volatile(
                        "mma.sync.aligned.m16n8k8.row.col.f32.tf32.tf32.f32 "
                        "{%0,%1,%2,%3}, {%4,%5,%6,%7}, {%8,%9}, {%0,%1,%2,%3};\n"
                        : "+f"(acc[mf][nf][0]), "+f"(acc[mf][nf][1]),
                          "+f"(acc[mf][nf][2]), "+f"(acc[mf][nf][3])
                        : "r"(af[mf][0]), "r"(af[mf][1]), "r"(af[mf][2]), "r"(af[mf][3]),
                          "r"(bf[nf][0]), "r"(bf[nf][1]));
                }
        }

        // stage next tile into the other buffer
        if (t + 1 < T) {
            const int nb = buf ^ 1;
#pragma unroll
            for (int i = 0; i < 2; ++i) {
                int lin = tid * 4 + i * 1024;
                int arr = lin >> 4, acn = lin & 15;
                float4 va = ra[i];
                va.x = to_tf32(va.x); va.y = to_tf32(va.y);
                va.z = to_tf32(va.z); va.w = to_tf32(va.w);
                *reinterpret_cast<float4*>(&As[nb][arr][acn]) = va;
                int brr = lin >> 7, bcn = lin & 127;
                float4 vb = rb[i];
                vb.x = to_tf32(vb.x); vb.y = to_tf32(vb.y);
                vb.z = to_tf32(vb.z); vb.w = to_tf32(vb.w);
                *reinterpret_cast<float4*>(&Bs[nb][brr][bcn]) = vb;
            }
        }
        __syncthreads();
        buf ^= 1;
    }

    // ---- epilogue ----
    const int nheads = N >> 6;
#pragma unroll
    for (int mf = 0; mf < 4; ++mf) {
        const int row0 = m0 + wm + mf * 16 + g;
        const int row1 = row0 + 8;
#pragma unroll
        for (int nf = 0; nf < 4; ++nf) {
            const int col0 = n0 + wn + nf * 8 + q * 2;
            float2 v01 = make_float2(acc[mf][nf][0], acc[mf][nf][1]);
            float2 v23 = make_float2(acc[mf][nf][2], acc[mf][nf][3]);
            if (mode == 1) {
                *reinterpret_cast<float2*>(&C[(size_t)row0 * N + col0]) = v01;
                *reinterpret_cast<float2*>(&C[(size_t)row1 * N + col0]) = v23;
            } else {
                const int h = col0 >> 6, d = col0 & 63;
                {
                    int b = row0 / S_, s = row0 % S_;
                    *reinterpret_cast<float2*>(
                        &C[((((size_t)b * nheads + h) * S_) + s) * DH_ + d]) = v01;
                }
                {
                    int b = row1 / S_, s = row1 % S_;
                    *reinterpret_cast<float2*>(
                        &C[((((size_t)b * nheads + h) * S_) + s) * DH_ + d]) = v23;
                }
            }
        }
    }
}

// ---------------------------------------------------------------------------
// L2-normalize (over D=64) then RoPE, in-place. One warp per (b,h,s) row.
// ---------------------------------------------------------------------------
__global__ void norm_rope_kernel(float* __restrict__ t, const float* __restrict__ cosb,
                                 const float* __restrict__ sinb, int nrows)
{
    int gwarp = (blockIdx.x * blockDim.x + threadIdx.x) >> 5;
    int lane  = threadIdx.x & 31;
    if (gwarp >= nrows) return;
    int s = gwarp % S_;
    float* row = t + (size_t)gwarp * DH_;

    float e1 = row[lane];
    float e2 = row[lane + 32];
    float ss = e1 * e1 + e2 * e2;
#pragma unroll
    for (int o = 16; o; o >>= 1) ss += __shfl_xor_sync(0xffffffffu, ss, o);
    float inv = 1.0f / (sqrtf(ss) + 1e-8f);
    e1 *= inv; e2 *= inv;

    float c  = cosb[s * 32 + lane];
    float sn = sinb[s * 32 + lane];
    row[lane]      = e1 * c  - e2 * sn;
    row[lane + 32] = e1 * sn + e2 * c;
}

// ---------------------------------------------------------------------------
// Attention: block = 8 consecutive queries of one (b,h); 8 warps, 1 query/warp.
// K/V staged in shared 64-key chunks. Sliding window 256 + 4 global keys.
// Softcap 15*tanh(s/15) applied pre-mask (matches reference). Online softmax.
// ---------------------------------------------------------------------------
__global__ void attn_kernel(const float* __restrict__ Q, const float* __restrict__ Kb,
                            const float* __restrict__ Vb, float* __restrict__ ctx)
{
    __shared__ float Ks[64][65];
    __shared__ float Vs[64][65];
    __shared__ float Qs[8][64];

    const int lane = threadIdx.x & 31;
    const int w    = threadIdx.x >> 5;
    const int b    = blockIdx.z;
    const int h    = blockIdx.y;
    const int q0   = blockIdx.x * 8;
    const int q    = q0 + w;
    const int kvh  = h / NG_;

    const float* qrow = Q + ((((size_t)b * H_ + h) * S_) + q) * DH_;
    Qs[w][lane]      = qrow[lane];
    Qs[w][lane + 32] = qrow[lane + 32];

    const float* Kbase = Kb + (((size_t)b * KVH_ + kvh) * S_) * DH_;
    const float* Vbase = Vb + (((size_t)b * KVH_ + kvh) * S_) * DH_;

    float m_run = -INFINITY, l_run = 0.f, o0 = 0.f, o1 = 0.f;

    int q_lo = q0 - (WINDOW_ - 1); if (q_lo < 0) q_lo = 0;
    const int c_lo  = q_lo >> 6;
    const int c_hi  = (q0 + 7) >> 6;
    const int extra = (c_lo > 0) ? 1 : 0;
    const int nch   = c_hi - c_lo + 1 + extra;

    for (int it = 0; it < nch; ++it) {
        int c = extra ? (it == 0 ? 0 : c_lo + it - 1) : (c_lo + it);

        __syncthreads();
        // cooperative load of 64 keys + values (4096 floats each)
        for (int i = threadIdx.x; i < 1024; i += 256) {
            int r  = i >> 4;
            int c4 = (i & 15) * 4;
            const float* kp = &Kbase[((size_t)(c * 64 + r)) * DH_ + c4];
            const float* vp = &Vbase[((size_t)(c * 64 + r)) * DH_ + c4];
            float4 kv = *reinterpret_cast<const float4*>(kp);
            float4 vv = *reinterpret_cast<const float4*>(vp);
            Ks[r][c4] = kv.x; Ks[r][c4 + 1] = kv.y; Ks[r][c4 + 2] = kv.z; Ks[r][c4 + 3] = kv.w;
            Vs[r][c4] = vv.x; Vs[r][c4 + 1] = vv.y; Vs[r][c4 + 2] = vv.z; Vs[r][c4 + 3] = vv.w;
        }
        __syncthreads();

        const int j0 = lane, j1 = lane + 32;
        const int k0a = c * 64 + j0, k1a = c * 64 + j1;

        float s0 = 0.f, s1 = 0.f;
#pragma unroll
        for (int d = 0; d < 64; ++d) {
            float qd = Qs[w][d];
            s0 += qd * Ks[j0][d];
            s1 += qd * Ks[j1][d];
        }
        s0 *= ATTN_SCALE_;  s1 *= ATTN_SCALE_;
        s0 = 15.0f * tanhf(s0 * (1.0f / 15.0f));
        s1 = 15.0f * tanhf(s1 * (1.0f / 15.0f));

        bool v0 = (k0a <= q) && ((k0a + WINDOW_ > q) || (k0a < NGLOBAL_));
        bool v1 = (k1a <= q) && ((k1a + WINDOW_ > q) || (k1a < NGLOBAL_));
        if (!v0) s0 = -INFINITY;
        if (!v1) s1 = -INFINITY;

        float cm = fmaxf(s0, s1);
#pragma unroll
        for (int o = 16; o; o >>= 1) cm = fmaxf(cm, __shfl_xor_sync(0xffffffffu, cm, o));

        if (cm != -INFINITY) {
            float m_new = fmaxf(m_run, cm);
            float alpha = __expf(m_run - m_new);
            o0 *= alpha; o1 *= alpha; l_run *= alpha;

            float p0 = __expf(s0 - m_new);
            float p1 = __expf(s1 - m_new);
            float ps = p0 + p1;
#pragma unroll
            for (int o = 16; o; o >>= 1) ps += __shfl_xor_sync(0xffffffffu, ps, o);
            l_run += ps;

#pragma unroll
            for (int j = 0; j < 32; ++j) {
                float wj = __shfl_sync(0xffffffffu, p0, j);
                o0 += wj * Vs[j][lane];
                o1 += wj * Vs[j][lane + 32];
            }
#pragma unroll
            for (int j = 0; j < 32; ++j) {
                float wj = __shfl_sync(0xffffffffu, p1, j);
                o0 += wj * Vs[32 + j][lane];
                o1 += wj * Vs[32 + j][lane + 32];
            }
            m_run = m_new;
        }
    }

    float invl = 1.0f / l_run;
    float* crow = ctx + ((((size_t)b * S_ + q) * H_) + h) * DH_;
    crow[lane]      = o0 * invl;
    crow[lane + 32] = o1 * invl;
}

// ---------------------------------------------------------------------------
// Launch
// ---------------------------------------------------------------------------
extern "C" void kernel_launch(void* const* d_in, const int* in_sizes, int n_in,
                              void* d_out, int out_size)
{
    const float* x    = (const float*)d_in[0];
    const float* cosb = (const float*)d_in[1];
    const float* sinb = (const float*)d_in[2];
    // d_in[3] = mask (pure causal) — computed analytically, unused
    const float* Wq   = (const float*)d_in[4];
    const float* Wk   = (const float*)d_in[5];
    const float* Wv   = (const float*)d_in[6];
    const float* Wo   = (const float*)d_in[7];
    float* out        = (float*)d_out;

    float *qp, *kp, *vp, *cp;
    cudaGetSymbolAddress((void**)&qp, g_q);
    cudaGetSymbolAddress((void**)&kp, g_k);
    cudaGetSymbolAddress((void**)&vp, g_v);
    cudaGetSymbolAddress((void**)&cp, g_ctx);

    const int M = B_ * S_;     // 4096
    dim3 t(256);

    // QKV projections (epilogue scatters to [b,h,s,d])
    tf32_gemm<<<dim3(H_ * DH_ / BN,   M / BM), t>>>(x, Wq, qp, M, H_ * DH_,   DM_, 0);
    tf32_gemm<<<dim3(KVH_ * DH_ / BN, M / BM), t>>>(x, Wk, kp, M, KVH_ * DH_, DM_, 0);
    tf32_gemm<<<dim3(KVH_ * DH_ / BN, M / BM), t>>>(x, Wv, vp, M, KVH_ * DH_, DM_, 0);

    // L2-norm + RoPE (q and k)
    norm_rope_kernel<<<(B_ * H_ * S_)   / 8, t>>>(qp, cosb, sinb, B_ * H_ * S_);
    norm_rope_kernel<<<(B_ * KVH_ * S_) / 8, t>>>(kp, cosb, sinb, B_ * KVH_ * S_);

    // Attention
    attn_kernel<<<dim3(S_ / 8, H_, B_), t>>>(qp, kp, vp, cp);

    // Output projection (row-major into d_out)
    tf32_gemm<<<dim3(DM_ / BN, M / BM), t>>>(cp, Wo, out, M, DM_, DM_, 1);
}

// round 5
// speedup vs baseline: 3.4704x; 2.3442x over previous
#include <cuda_runtime.h>
#include <cuda_bf16.h>
#include <math.h>
#include <stdint.h>

// Problem constants
#define B_   2
#define S_   2048
#define DM_  1024
#define H_   16
#define KVH_ 4
#define NG_  4          // H_/KVH_
#define DH_  64
#define WINDOW_ 256
#define NGLOBAL_ 4
#define ATTN_SCALE_ 0.125f   // 1/sqrt(64)

// Scratch (static device allocations; no cudaMalloc allowed)
__device__ float g_q[(size_t)B_ * H_ * S_ * DH_];     // [b,h,s,d]
__device__ float g_k[(size_t)B_ * KVH_ * S_ * DH_];   // [b,kvh,s,d]
__device__ float g_v[(size_t)B_ * KVH_ * S_ * DH_];   // [b,kvh,s,d]
__device__ float g_ctx[(size_t)B_ * S_ * H_ * DH_];   // [b,s,h,d] == row-major [4096,1024]

__device__ __forceinline__ float to_tf32(float x) {
    asm("cvt.rna.tf32.f32 %0, %0;" : "+f"(x));
    return x;
}

#define MMA_TF32(D, A, B)                                                     \
    asm volatile(                                                             \
        "mma.sync.aligned.m16n8k8.row.col.f32.tf32.tf32.f32 "                 \
        "{%0,%1,%2,%3}, {%4,%5,%6,%7}, {%8,%9}, {%0,%1,%2,%3};\n"             \
        : "+f"((D)[0]), "+f"((D)[1]), "+f"((D)[2]), "+f"((D)[3])              \
        : "r"((A)[0]), "r"((A)[1]), "r"((A)[2]), "r"((A)[3]),                 \
          "r"((B)[0]), "r"((B)[1]))

// ---------------------------------------------------------------------------
// tf32 tensor-core GEMM: C = A[M,K] @ W[K,N], fp32 accumulate. (unchanged)
// ---------------------------------------------------------------------------
#define BM 128
#define BN 128
#define BK 16

__global__ __launch_bounds__(256) void tf32_gemm(const float* __restrict__ A,
                                                 const float* __restrict__ W,
                                                 float* __restrict__ C,
                                                 int M, int N, int K, int mode)
{
    __shared__ float As[2][BM][20];
    __shared__ float Bs[2][BK][136];

    const int tid  = threadIdx.x;
    const int wid  = tid >> 5;
    const int lane = tid & 31;
    const int g    = lane >> 2;
    const int q    = lane & 3;
    const int m0   = blockIdx.y * BM;
    const int n0   = blockIdx.x * BN;
    const int wm   = (wid >> 2) * 64;
    const int wn   = (wid & 3) * 32;

    float acc[4][4][4];
#pragma unroll
    for (int i = 0; i < 4; ++i)
#pragma unroll
        for (int j = 0; j < 4; ++j)
#pragma unroll
            for (int r = 0; r < 4; ++r) acc[i][j][r] = 0.f;

    float4 ra[2], rb[2];
    const int T = K / BK;

    {
        const int k0 = 0;
#pragma unroll
        for (int i = 0; i < 2; ++i) {
            int lin = tid * 4 + i * 1024;
            int arr = lin >> 4, acn = lin & 15;
            ra[i] = *reinterpret_cast<const float4*>(&A[(size_t)(m0 + arr) * K + k0 + acn]);
            int brr = lin >> 7, bcn = lin & 127;
            rb[i] = *reinterpret_cast<const float4*>(&W[(size_t)(k0 + brr) * N + n0 + bcn]);
        }
#pragma unroll
        for (int i = 0; i < 2; ++i) {
            int lin = tid * 4 + i * 1024;
            int arr = lin >> 4, acn = lin & 15;
            float4 va = ra[i];
            va.x = to_tf32(va.x); va.y = to_tf32(va.y);
            va.z = to_tf32(va.z); va.w = to_tf32(va.w);
            *reinterpret_cast<float4*>(&As[0][arr][acn]) = va;
            int brr = lin >> 7, bcn = lin & 127;
            float4 vb = rb[i];
            vb.x = to_tf32(vb.x); vb.y = to_tf32(vb.y);
            vb.z = to_tf32(vb.z); vb.w = to_tf32(vb.w);
            *reinterpret_cast<float4*>(&Bs[0][brr][bcn]) = vb;
        }
    }
    __syncthreads();

    int buf = 0;
    for (int t = 0; t < T; ++t) {
        if (t + 1 < T) {
            const int k0 = (t + 1) * BK;
#pragma unroll
            for (int i = 0; i < 2; ++i) {
                int lin = tid * 4 + i * 1024;
                int arr = lin >> 4, acn = lin & 15;
                ra[i] = *reinterpret_cast<const float4*>(&A[(size_t)(m0 + arr) * K + k0 + acn]);
                int brr = lin >> 7, bcn = lin & 127;
                rb[i] = *reinterpret_cast<const float4*>(&W[(size_t)(k0 + brr) * N + n0 + bcn]);
            }
        }

#pragma unroll
        for (int kk = 0; kk < 2; ++kk) {
            const int kb = kk * 8;
            uint32_t af[4][4], bf[4][2];
#pragma unroll
            for (int mf = 0; mf < 4; ++mf) {
                const int mrow = wm + mf * 16;
                af[mf][0] = __float_as_uint(As[buf][mrow + g    ][kb + q    ]);
                af[mf][1] = __float_as_uint(As[buf][mrow + g + 8][kb + q    ]);
                af[mf][2] = __float_as_uint(As[buf][mrow + g    ][kb + q + 4]);
                af[mf][3] = __float_as_uint(As[buf][mrow + g + 8][kb + q + 4]);
            }
#pragma unroll
            for (int nf = 0; nf < 4; ++nf) {
                const int ncol = wn + nf * 8 + g;
                bf[nf][0] = __float_as_uint(Bs[buf][kb + q    ][ncol]);
                bf[nf][1] = __float_as_uint(Bs[buf][kb + q + 4][ncol]);
            }
#pragma unroll
            for (int mf = 0; mf < 4; ++mf)
#pragma unroll
                for (int nf = 0; nf < 4; ++nf)
                    MMA_TF32(acc[mf][nf], af[mf], bf[nf]);
        }

        if (t + 1 < T) {
            const int nb = buf ^ 1;
#pragma unroll
            for (int i = 0; i < 2; ++i) {
                int lin = tid * 4 + i * 1024;
                int arr = lin >> 4, acn = lin & 15;
                float4 va = ra[i];
                va.x = to_tf32(va.x); va.y = to_tf32(va.y);
                va.z = to_tf32(va.z); va.w = to_tf32(va.w);
                *reinterpret_cast<float4*>(&As[nb][arr][acn]) = va;
                int brr = lin >> 7, bcn = lin & 127;
                float4 vb = rb[i];
                vb.x = to_tf32(vb.x); vb.y = to_tf32(vb.y);
                vb.z = to_tf32(vb.z); vb.w = to_tf32(vb.w);
                *reinterpret_cast<float4*>(&Bs[nb][brr][bcn]) = vb;
            }
        }
        __syncthreads();
        buf ^= 1;
    }

    const int nheads = N >> 6;
#pragma unroll
    for (int mf = 0; mf < 4; ++mf) {
        const int row0 = m0 + wm + mf * 16 + g;
        const int row1 = row0 + 8;
#pragma unroll
        for (int nf = 0; nf < 4; ++nf) {
            const int col0 = n0 + wn + nf * 8 + q * 2;
            float2 v01 = make_float2(acc[mf][nf][0], acc[mf][nf][1]);
            float2 v23 = make_float2(acc[mf][nf][2], acc[mf][nf][3]);
            if (mode == 1) {
                *reinterpret_cast<float2*>(&C[(size_t)row0 * N + col0]) = v01;
                *reinterpret_cast<float2*>(&C[(size_t)row1 * N + col0]) = v23;
            } else {
                const int h = col0 >> 6, d = col0 & 63;
                {
                    int b = row0 / S_, s = row0 % S_;
                    *reinterpret_cast<float2*>(
                        &C[((((size_t)b * nheads + h) * S_) + s) * DH_ + d]) = v01;
                }
                {
                    int b = row1 / S_, s = row1 % S_;
                    *reinterpret_cast<float2*>(
                        &C[((((size_t)b * nheads + h) * S_) + s) * DH_ + d]) = v23;
                }
            }
        }
    }
}

// ---------------------------------------------------------------------------
// L2-normalize (over D=64) then RoPE, in-place. One warp per (b,h,s) row.
// ---------------------------------------------------------------------------
__global__ void norm_rope_kernel(float* __restrict__ t, const float* __restrict__ cosb,
                                 const float* __restrict__ sinb, int nrows)
{
    int gwarp = (blockIdx.x * blockDim.x + threadIdx.x) >> 5;
    int lane  = threadIdx.x & 31;
    if (gwarp >= nrows) return;
    int s = gwarp % S_;
    float* row = t + (size_t)gwarp * DH_;

    float e1 = row[lane];
    float e2 = row[lane + 32];
    float ss = e1 * e1 + e2 * e2;
#pragma unroll
    for (int o = 16; o; o >>= 1) ss += __shfl_xor_sync(0xffffffffu, ss, o);
    float inv = 1.0f / (sqrtf(ss) + 1e-8f);
    e1 *= inv; e2 *= inv;

    float c  = cosb[s * 32 + lane];
    float sn = sinb[s * 32 + lane];
    row[lane]      = e1 * c  - e2 * sn;
    row[lane + 32] = e1 * sn + e2 * c;
}

// ---------------------------------------------------------------------------
// Flash attention w/ tensor cores.
// Block = 64 queries of one (b,h); 128 threads = 4 warps; warp tile m16 x n64.
// K chunk 64 keys staged in smem (pitch 68, conflict-free), V pitch 72.
// P routed through the (dead) K buffer for frag-layout conversion.
// Sliding window 256 + 4 global keys; softcap pre-mask; online softmax.
// ---------------------------------------------------------------------------
__global__ __launch_bounds__(128) void attn_mma_kernel(const float* __restrict__ Q,
                                                       const float* __restrict__ Kb,
                                                       const float* __restrict__ Vb,
                                                       float* __restrict__ ctx)
{
    __shared__ float Ks[64][68];   // K chunk; aliased as P after QK^T
    __shared__ float Vs[64][72];

    const int tid  = threadIdx.x;
    const int lane = tid & 31;
    const int w    = tid >> 5;
    const int g    = lane >> 2;    // row-in-frag 0..7
    const int qq   = lane & 3;     // col-group 0..3
    const int b    = blockIdx.z;
    const int h    = blockIdx.y;
    const int q0   = blockIdx.x * 64;
    const int kvh  = h / NG_;
    const int mrow = w * 16;

    const float* Qbase = Q  + ((((size_t)b * H_ + h) * S_) + q0) * DH_;
    const float* Kbase = Kb + (((size_t)b * KVH_ + kvh) * S_) * DH_;
    const float* Vbase = Vb + (((size_t)b * KVH_ + kvh) * S_) * DH_;

    // ---- stage Q tile through Ks, pull A-frags (8 k-steps) into registers ----
    for (int i = tid; i < 1024; i += 128) {
        int r = i >> 4, c4 = (i & 15) * 4;
        float4 v = *reinterpret_cast<const float4*>(&Qbase[(size_t)r * DH_ + c4]);
        v.x = to_tf32(v.x); v.y = to_tf32(v.y);
        v.z = to_tf32(v.z); v.w = to_tf32(v.w);
        *reinterpret_cast<float4*>(&Ks[r][c4]) = v;
    }
    __syncthreads();
    uint32_t qf[8][4];
#pragma unroll
    for (int ks = 0; ks < 8; ++ks) {
        const int kb = ks * 8;
        qf[ks][0] = __float_as_uint(Ks[mrow + g    ][kb + qq    ]);
        qf[ks][1] = __float_as_uint(Ks[mrow + g + 8][kb + qq    ]);
        qf[ks][2] = __float_as_uint(Ks[mrow + g    ][kb + qq + 4]);
        qf[ks][3] = __float_as_uint(Ks[mrow + g + 8][kb + qq + 4]);
    }

    float o[8][4];
#pragma unroll
    for (int nf = 0; nf < 8; ++nf)
#pragma unroll
        for (int j = 0; j < 4; ++j) o[nf][j] = 0.f;
    float m0 = -INFINITY, m1 = -INFINITY, l0 = 0.f, l1 = 0.f;

    const int row0 = q0 + mrow + g;
    const int row1 = row0 + 8;

    int q_lo = q0 - (WINDOW_ - 1); if (q_lo < 0) q_lo = 0;
    const int c_lo = q_lo >> 6;
    const int c_hi = q0 >> 6;
    const int nch  = c_hi - c_lo + 1 + (c_lo > 0 ? 1 : 0);

    for (int it = 0; it < nch; ++it) {
        const int c = (c_lo > 0) ? (it == 0 ? 0 : c_lo + it - 1) : (c_lo + it);

        __syncthreads();   // previous chunk's PV (reads Ks/Vs) fully done
        for (int i = tid; i < 1024; i += 128) {
            int r = i >> 4, c4 = (i & 15) * 4;
            float4 kv = *reinterpret_cast<const float4*>(&Kbase[((size_t)(c * 64 + r)) * DH_ + c4]);
            float4 vv = *reinterpret_cast<const float4*>(&Vbase[((size_t)(c * 64 + r)) * DH_ + c4]);
            kv.x = to_tf32(kv.x); kv.y = to_tf32(kv.y);
            kv.z = to_tf32(kv.z); kv.w = to_tf32(kv.w);
            vv.x = to_tf32(vv.x); vv.y = to_tf32(vv.y);
            vv.z = to_tf32(vv.z); vv.w = to_tf32(vv.w);
            *reinterpret_cast<float4*>(&Ks[r][c4]) = kv;
            *reinterpret_cast<float4*>(&Vs[r][c4]) = vv;
        }
        __syncthreads();

        // ---- S = Q K^T (m16 x n64 x k64) ----
        float s[8][4];
#pragma unroll
        for (int nf = 0; nf < 8; ++nf)
#pragma unroll
            for (int j = 0; j < 4; ++j) s[nf][j] = 0.f;

#pragma unroll
        for (int ks = 0; ks < 8; ++ks) {
            const int kb = ks * 8;
            uint32_t bf[8][2];
#pragma unroll
            for (int nf = 0; nf < 8; ++nf) {
                const int key = nf * 8 + g;
                bf[nf][0] = __float_as_uint(Ks[key][kb + qq    ]);
                bf[nf][1] = __float_as_uint(Ks[key][kb + qq + 4]);
            }
#pragma unroll
            for (int nf = 0; nf < 8; ++nf)
                MMA_TF32(s[nf], qf[ks], bf[nf]);
        }

        // ---- softcap + mask + row max ----
        float rmax0 = -INFINITY, rmax1 = -INFINITY;
#pragma unroll
        for (int nf = 0; nf < 8; ++nf) {
            const int kc0 = c * 64 + nf * 8 + 2 * qq;
            const int kc1 = kc0 + 1;
#pragma unroll
            for (int j = 0; j < 4; ++j) {
                const int kc = (j & 1) ? kc1 : kc0;
                const int qr = (j < 2) ? row0 : row1;
                float x = s[nf][j] * ATTN_SCALE_;
                float e = __expf(x * (2.0f / 15.0f));
                x = 15.0f * ((e - 1.0f) / (e + 1.0f));
                bool valid = (kc <= qr) && ((kc + WINDOW_ > qr) || (kc < NGLOBAL_));
                x = valid ? x : -INFINITY;
                s[nf][j] = x;
                if (j < 2) rmax0 = fmaxf(rmax0, x); else rmax1 = fmaxf(rmax1, x);
            }
        }
        rmax0 = fmaxf(rmax0, __shfl_xor_sync(0xffffffffu, rmax0, 1));
        rmax0 = fmaxf(rmax0, __shfl_xor_sync(0xffffffffu, rmax0, 2));
        rmax1 = fmaxf(rmax1, __shfl_xor_sync(0xffffffffu, rmax1, 1));
        rmax1 = fmaxf(rmax1, __shfl_xor_sync(0xffffffffu, rmax1, 2));

        const float mn0 = fmaxf(fmaxf(m0, rmax0), -1e30f);
        const float mn1 = fmaxf(fmaxf(m1, rmax1), -1e30f);
        const float a0 = __expf(m0 - mn0);
        const float a1 = __expf(m1 - mn1);

        float rs0 = 0.f, rs1 = 0.f;
#pragma unroll
        for (int nf = 0; nf < 8; ++nf) {
            float p0 = __expf(s[nf][0] - mn0);
            float p1 = __expf(s[nf][1] - mn0);
            float p2 = __expf(s[nf][2] - mn1);
            float p3 = __expf(s[nf][3] - mn1);
            rs0 += p0 + p1; rs1 += p2 + p3;
            s[nf][0] = p0; s[nf][1] = p1; s[nf][2] = p2; s[nf][3] = p3;
        }
        rs0 += __shfl_xor_sync(0xffffffffu, rs0, 1);
        rs0 += __shfl_xor_sync(0xffffffffu, rs0, 2);
        rs1 += __shfl_xor_sync(0xffffffffu, rs1, 1);
        rs1 += __shfl_xor_sync(0xffffffffu, rs1, 2);
        l0 = l0 * a0 + rs0;
        l1 = l1 * a1 + rs1;
#pragma unroll
        for (int nf = 0; nf < 8; ++nf) {
            o[nf][0] *= a0; o[nf][1] *= a0;
            o[nf][2] *= a1; o[nf][3] *= a1;
        }
        m0 = mn0; m1 = mn1;

        __syncthreads();   // all warps done reading Ks -> safe to overwrite with P

        // ---- store P frags (tf32) into Ks region ----
#pragma unroll
        for (int nf = 0; nf < 8; ++nf) {
            const int col = nf * 8 + 2 * qq;
            *reinterpret_cast<float2*>(&Ks[mrow + g    ][col]) =
                make_float2(to_tf32(s[nf][0]), to_tf32(s[nf][1]));
            *reinterpret_cast<float2*>(&Ks[mrow + g + 8][col]) =
                make_float2(to_tf32(s[nf][2]), to_tf32(s[nf][3]));
        }
        __syncwarp();      // each warp reads only its own 16 P rows

        // ---- O += P V (m16 x n64 x k64) ----
#pragma unroll
        for (int ks = 0; ks < 8; ++ks) {
            const int kb = ks * 8;
            uint32_t af[4];
            af[0] = __float_as_uint(Ks[mrow + g    ][kb + qq    ]);
            af[1] = __float_as_uint(Ks[mrow + g + 8][kb + qq    ]);
            af[2] = __float_as_uint(Ks[mrow + g    ][kb + qq + 4]);
            af[3] = __float_as_uint(Ks[mrow + g + 8][kb + qq + 4]);
            uint32_t bfv[8][2];
#pragma unroll
            for (int nf = 0; nf < 8; ++nf) {
                const int d = nf * 8 + g;
                bfv[nf][0] = __float_as_uint(Vs[kb + qq    ][d]);
                bfv[nf][1] = __float_as_uint(Vs[kb + qq + 4][d]);
            }
#pragma unroll
            for (int nf = 0; nf < 8; ++nf)
                MMA_TF32(o[nf], af, bfv[nf]);
        }
    }

    // ---- epilogue: normalize and write ctx[b][s][h][d] ----
    const float inv0 = 1.0f / l0;
    const float inv1 = 1.0f / l1;
    float* c0p = ctx + ((((size_t)b * S_ + row0) * H_) + h) * DH_;
    float* c1p = ctx + ((((size_t)b * S_ + row1) * H_) + h) * DH_;
#pragma unroll
    for (int nf = 0; nf < 8; ++nf) {
        const int d = nf * 8 + 2 * qq;
        *reinterpret_cast<float2*>(&c0p[d]) = make_float2(o[nf][0] * inv0, o[nf][1] * inv0);
        *reinterpret_cast<float2*>(&c1p[d]) = make_float2(o[nf][2] * inv1, o[nf][3] * inv1);
    }
}

// ---------------------------------------------------------------------------
// Launch
// ---------------------------------------------------------------------------
extern "C" void kernel_launch(void* const* d_in, const int* in_sizes, int n_in,
                              void* d_out, int out_size)
{
    const float* x    = (const float*)d_in[0];
    const float* cosb = (const float*)d_in[1];
    const float* sinb = (const float*)d_in[2];
    // d_in[3] = mask (pure causal) — computed analytically, unused
    const float* Wq   = (const float*)d_in[4];
    const float* Wk   = (const float*)d_in[5];
    const float* Wv   = (const float*)d_in[6];
    const float* Wo   = (const float*)d_in[7];
    float* out        = (float*)d_out;

    float *qp, *kp, *vp, *cp;
    cudaGetSymbolAddress((void**)&qp, g_q);
    cudaGetSymbolAddress((void**)&kp, g_k);
    cudaGetSymbolAddress((void**)&vp, g_v);
    cudaGetSymbolAddress((void**)&cp, g_ctx);

    const int M = B_ * S_;     // 4096
    dim3 t(256);

    // QKV projections (epilogue scatters to [b,h,s,d])
    tf32_gemm<<<dim3(H_ * DH_ / BN,   M / BM), t>>>(x, Wq, qp, M, H_ * DH_,   DM_, 0);
    tf32_gemm<<<dim3(KVH_ * DH_ / BN, M / BM), t>>>(x, Wk, kp, M, KVH_ * DH_, DM_, 0);
    tf32_gemm<<<dim3(KVH_ * DH_ / BN, M / BM), t>>>(x, Wv, vp, M, KVH_ * DH_, DM_, 0);

    // L2-norm + RoPE (q and k)
    norm_rope_kernel<<<(B_ * H_ * S_)   / 8, t>>>(qp, cosb, sinb, B_ * H_ * S_);
    norm_rope_kernel<<<(B_ * KVH_ * S_) / 8, t>>>(kp, cosb, sinb, B_ * KVH_ * S_);

    // Flash attention (tensor cores)
    attn_mma_kernel<<<dim3(S_ / 64, H_, B_), dim3(128)>>>(qp, kp, vp, cp);

    // Output projection (row-major into d_out)
    tf32_gemm<<<dim3(DM_ / BN, M / BM), t>>>(cp, Wo, out, M, DM_, DM_, 1);
}

// round 7
// speedup vs baseline: 6.5442x; 1.8857x over previous
#include <cuda_runtime.h>
#include <cuda_fp16.h>
#include <math.h>
#include <stdint.h>

// Problem constants
#define B_   2
#define S_   2048
#define DM_  1024
#define H_   16
#define KVH_ 4
#define NG_  4          // H_/KVH_
#define DH_  64
#define WINDOW_ 256
#define NGLOBAL_ 4
#define ATTN_SCALE_ 0.125f   // 1/sqrt(64)
#define M_TOT (B_ * S_)      // 4096

// Scratch (static device allocations; no cudaMalloc allowed)
__device__ __half g_x16 [(size_t)M_TOT * DM_];            // x, fp16
__device__ __half g_wq16[(size_t)DM_ * DM_];              // Wq [k][n] fp16
__device__ __half g_wk16[(size_t)DM_ * (KVH_ * DH_)];     // Wk [k][n]
__device__ __half g_wv16[(size_t)DM_ * (KVH_ * DH_)];     // Wv [k][n]
__device__ __half g_wo16[(size_t)DM_ * DM_];              // Wo [k][n]
__device__ __half g_q16 [(size_t)B_ * H_ * S_ * DH_];     // [b,h,s,d]
__device__ __half g_k16 [(size_t)B_ * KVH_ * S_ * DH_];   // [b,kvh,s,d]
__device__ __half g_v16 [(size_t)B_ * KVH_ * S_ * DH_];   // [b,kvh,s,d]
__device__ __half g_ctx16[(size_t)M_TOT * DM_];           // [b,s,h,d] fp16

#define MMA_F16(D, A, B)                                                      \
    asm volatile(                                                             \
        "mma.sync.aligned.m16n8k16.row.col.f32.f16.f16.f32 "                  \
        "{%0,%1,%2,%3}, {%4,%5,%6,%7}, {%8,%9}, {%0,%1,%2,%3};\n"             \
        : "+f"((D)[0]), "+f"((D)[1]), "+f"((D)[2]), "+f"((D)[3])              \
        : "r"((A)[0]), "r"((A)[1]), "r"((A)[2]), "r"((A)[3]),                 \
          "r"((B)[0]), "r"((B)[1]))

#define LDMX4(R, addr)                                                        \
    asm volatile("ldmatrix.sync.aligned.m8n8.x4.shared.b16 {%0,%1,%2,%3}, [%4];" \
        : "=r"((R)[0]), "=r"((R)[1]), "=r"((R)[2]), "=r"((R)[3]) : "r"(addr))

#define LDMX4T(R, addr)                                                       \
    asm volatile("ldmatrix.sync.aligned.m8n8.x4.trans.shared.b16 {%0,%1,%2,%3}, [%4];" \
        : "=r"((R)[0]), "=r"((R)[1]), "=r"((R)[2]), "=r"((R)[3]) : "r"(addr))

__device__ __forceinline__ uint32_t smem_u32(const void* p) {
    uint32_t a;
    asm("{ .reg .u64 t; cvta.to.shared.u64 t, %1; cvt.u32.u64 %0, t; }" : "=r"(a) : "l"(p));
    return a;
}

// ---------------------------------------------------------------------------
// fp32 -> fp16 conversion kernels
// ---------------------------------------------------------------------------
__global__ void cvt_half_kernel(const float* __restrict__ in, __half* __restrict__ out, int n4)
{
    int i = blockIdx.x * blockDim.x + threadIdx.x;
    int stride = gridDim.x * blockDim.x;
    for (; i < n4; i += stride) {
        float4 v = ((const float4*)in)[i];
        __half2 h0 = __floats2half2_rn(v.x, v.y);
        __half2 h1 = __floats2half2_rn(v.z, v.w);
        ((__half2*)out)[2 * i]     = h0;
        ((__half2*)out)[2 * i + 1] = h1;
    }
}

// Fused weight conversion: wq (262144 f4) | wk (65536) | wv (65536) | wo (262144)
__global__ void cvt_weights_kernel(const float* __restrict__ wq, const float* __restrict__ wk,
                                   const float* __restrict__ wv, const float* __restrict__ wo,
                                   __half* __restrict__ oq, __half* __restrict__ ok,
                                   __half* __restrict__ ov, __half* __restrict__ oo)
{
    int i = blockIdx.x * blockDim.x + threadIdx.x;
    int stride = gridDim.x * blockDim.x;
    for (; i < 655360; i += stride) {
        const float* src; __half* dst; int j;
        if (i < 262144)      { src = wq; dst = oq; j = i; }
        else if (i < 327680) { src = wk; dst = ok; j = i - 262144; }
        else if (i < 393216) { src = wv; dst = ov; j = i - 327680; }
        else                 { src = wo; dst = oo; j = i - 393216; }
        float4 v = ((const float4*)src)[j];
        ((__half2*)dst)[2 * j]     = __floats2half2_rn(v.x, v.y);
        ((__half2*)dst)[2 * j + 1] = __floats2half2_rn(v.z, v.w);
    }
}

// ---------------------------------------------------------------------------
// fp16 tensor-core GEMM: C = A[M,1024] @ W[1024,N], fp32 accumulate.
// BM=128, BN=128, BK=32. 256 threads = 8 warps (2m x 4n), warp tile 64x32.
// A smem [m][k] pitch 40 halves; W smem [k][n] pitch 136 halves.
// A frags via ldmatrix, W frags via ldmatrix.trans. Double-buffered.
// mode 0 (QKV fused, grid.x=12): bx<8 -> Q, {8,9} -> K, {10,11} -> V;
//   fp16 epilogue scatters to [b,h,s,d].
// mode 1 (grid.x=8): fp32 row-major out[m*1024 + n].
// ---------------------------------------------------------------------------
#define APITCH 40
#define BPITCH 136

__global__ __launch_bounds__(256) void h16_gemm(const __half* __restrict__ A,
                                                const __half* __restrict__ WQ,
                                                const __half* __restrict__ WK,
                                                const __half* __restrict__ WV,
                                                void* oQ, void* oK, void* oV, int mode)
{
    __shared__ __align__(16) __half As[2][128 * APITCH];
    __shared__ __align__(16) __half Bs[2][32 * BPITCH];

    const int tid  = threadIdx.x;
    const int wid  = tid >> 5;
    const int lane = tid & 31;
    const int g    = lane >> 2;
    const int q    = lane & 3;
    const int bx   = blockIdx.x;
    const int m0   = blockIdx.y * 128;
    const int wm   = (wid >> 2) * 64;
    const int wn   = (wid & 3) * 32;

    const __half* W; void* outp; int N, n0, nh;
    if (mode == 1)    { W = WQ; outp = oQ; N = 1024; n0 = bx * 128;        nh = H_; }
    else if (bx < 8)  { W = WQ; outp = oQ; N = 1024; n0 = bx * 128;        nh = H_; }
    else if (bx < 10) { W = WK; outp = oK; N = 256;  n0 = (bx - 8) * 128;  nh = KVH_; }
    else              { W = WV; outp = oV; N = 256;  n0 = (bx - 10) * 128; nh = KVH_; }

    float acc[4][4][4];
#pragma unroll
    for (int i = 0; i < 4; ++i)
#pragma unroll
        for (int j = 0; j < 4; ++j)
#pragma unroll
            for (int r = 0; r < 4; ++r) acc[i][j][r] = 0.f;

    // staging geometry
    const __half* aSrc = A + (size_t)(m0 + (tid >> 1)) * DM_ + (tid & 1) * 16;
    const __half* bSrc = W + (size_t)(tid >> 3) * N + n0 + (tid & 7) * 16;
    const int aOff = (tid >> 1) * APITCH + (tid & 1) * 16;
    const int bOff = (tid >> 3) * BPITCH + (tid & 7) * 16;

    const uint32_t sA0 = smem_u32(As[0]);
    const uint32_t sA1 = smem_u32(As[1]);
    const uint32_t sB0 = smem_u32(Bs[0]);
    const uint32_t sB1 = smem_u32(Bs[1]);

    // ldmatrix per-lane base offsets (half units)
    // A frag (mf, kk): row = wm + mf*16 + (lane&7) + 8*((lane>>3)&1), col = kk*16 + 8*(lane>>4)
    const int aFragRow = wm + (lane & 7) + 8 * ((lane >> 3) & 1);
    const int aFragCol = 8 * (lane >> 4);
    // W frag (np, kk): row = kk*16 + (lane&7) + 8*((lane>>3)&1), col = wn + np*16 + 8*(lane>>4)
    const int bFragRow = (lane & 7) + 8 * ((lane >> 3) & 1);
    const int bFragCol = wn + 8 * (lane >> 4);

    uint4 ra[2], rb[2];
    // prologue: tile 0
#pragma unroll
    for (int i = 0; i < 2; ++i) {
        ra[i] = *(const uint4*)(aSrc + i * 8);
        rb[i] = *(const uint4*)(bSrc + i * 8);
    }
#pragma unroll
    for (int i = 0; i < 2; ++i) {
        *(uint4*)(&As[0][aOff + i * 8]) = ra[i];
        *(uint4*)(&Bs[0][bOff + i * 8]) = rb[i];
    }
    __syncthreads();

    int buf = 0;
    const int T = DM_ / 32;   // 32 tiles
    for (int t = 0; t < T; ++t) {
        if (t + 1 < T) {
            const __half* a2 = aSrc + (t + 1) * 32;
            const __half* b2 = bSrc + (size_t)(t + 1) * 32 * N;
#pragma unroll
            for (int i = 0; i < 2; ++i) {
                ra[i] = *(const uint4*)(a2 + i * 8);
                rb[i] = *(const uint4*)(b2 + i * 8);
            }
        }

        const uint32_t sA = buf ? sA1 : sA0;
        const uint32_t sB = buf ? sB1 : sB0;
#pragma unroll
        for (int kk = 0; kk < 2; ++kk) {
            uint32_t af[4][4], bf[2][4];
#pragma unroll
            for (int mf = 0; mf < 4; ++mf) {
                uint32_t addr = sA + (uint32_t)((aFragRow + mf * 16) * APITCH +
                                                kk * 16 + aFragCol) * 2;
                LDMX4(af[mf], addr);
            }
#pragma unroll
            for (int np = 0; np < 2; ++np) {
                uint32_t addr = sB + (uint32_t)((kk * 16 + bFragRow) * BPITCH +
                                                bFragCol + np * 16) * 2;
                LDMX4T(bf[np], addr);
            }
#pragma unroll
            for (int mf = 0; mf < 4; ++mf)
#pragma unroll
                for (int np = 0; np < 2; ++np) {
                    MMA_F16(acc[mf][np * 2],     af[mf], (&bf[np][0]));
                    MMA_F16(acc[mf][np * 2 + 1], af[mf], (&bf[np][2]));
                }
        }

        if (t + 1 < T) {
            const int nb = buf ^ 1;
#pragma unroll
            for (int i = 0; i < 2; ++i) {
                *(uint4*)(&As[nb][aOff + i * 8]) = ra[i];
                *(uint4*)(&Bs[nb][bOff + i * 8]) = rb[i];
            }
        }
        __syncthreads();
        buf ^= 1;
    }

    // epilogue
#pragma unroll
    for (int mf = 0; mf < 4; ++mf) {
        const int row0 = m0 + wm + mf * 16 + g;
        const int row1 = row0 + 8;
#pragma unroll
        for (int nf = 0; nf < 4; ++nf) {
            const int col0 = n0 + wn + nf * 8 + q * 2;
            if (mode == 1) {
                float* C = (float*)outp;
                *(float2*)(&C[(size_t)row0 * 1024 + col0]) =
                    make_float2(acc[mf][nf][0], acc[mf][nf][1]);
                *(float2*)(&C[(size_t)row1 * 1024 + col0]) =
                    make_float2(acc[mf][nf][2], acc[mf][nf][3]);
            } else {
                __half* C = (__half*)outp;
                const int h = col0 >> 6, d = col0 & 63;
                {
                    int b = row0 >> 11, s = row0 & (S_ - 1);
                    *(__half2*)(&C[((((size_t)b * nh + h) * S_) + s) * DH_ + d]) =
                        __floats2half2_rn(acc[mf][nf][0], acc[mf][nf][1]);
                }
                {
                    int b = row1 >> 11, s = row1 & (S_ - 1);
                    *(__half2*)(&C[((((size_t)b * nh + h) * S_) + s) * DH_ + d]) =
                        __floats2half2_rn(acc[mf][nf][2], acc[mf][nf][3]);
                }
            }
        }
    }
}

// ---------------------------------------------------------------------------
// L2-normalize (over D=64) then RoPE, fp16 in/out, in-place.
// One warp per row; q rows then k rows in a single launch.
// ---------------------------------------------------------------------------
#define NQROWS (B_ * H_ * S_)     // 65536
#define NKROWS (B_ * KVH_ * S_)   // 16384

__global__ void norm_rope16_kernel(__half* __restrict__ qh, __half* __restrict__ kh,
                                   const float* __restrict__ cosb, const float* __restrict__ sinb)
{
    int gwarp = (blockIdx.x * blockDim.x + threadIdx.x) >> 5;
    int lane  = threadIdx.x & 31;
    if (gwarp >= NQROWS + NKROWS) return;
    __half* row = (gwarp < NQROWS) ? (qh + (size_t)gwarp * DH_)
                                   : (kh + (size_t)(gwarp - NQROWS) * DH_);
    int s = gwarp & (S_ - 1);   // layout [b][h][s] -> row % S == s

    float e1 = __half2float(row[lane]);
    float e2 = __half2float(row[lane + 32]);
    float ss = e1 * e1 + e2 * e2;
#pragma unroll
    for (int o = 16; o; o >>= 1) ss += __shfl_xor_sync(0xffffffffu, ss, o);
    float inv = 1.0f / (sqrtf(ss) + 1e-8f);
    e1 *= inv; e2 *= inv;

    float c  = cosb[s * 32 + lane];
    float sn = sinb[s * 32 + lane];
    row[lane]      = __float2half_rn(e1 * c  - e2 * sn);
    row[lane + 32] = __float2half_rn(e1 * sn + e2 * c);
}

// ---------------------------------------------------------------------------
// Flash attention, fp16 mma (m16n8k16, fp32 accum).
// Block = 64 queries of one (b,h); 128 threads = 4 warps; warp tile m16 x n64.
// K/Q/P smem pitch 72 halves; V pitch 72. Q/P A-frags + K (non-trans) and
// V (trans) B-frags via ldmatrix. Online softmax as before.
// ---------------------------------------------------------------------------
#define KPITCH 72

__global__ __launch_bounds__(128) void attn_h16_kernel(const __half* __restrict__ Q,
                                                       const __half* __restrict__ Kb,
                                                       const __half* __restrict__ Vb,
                                                       __half* __restrict__ ctx)
{
    __shared__ __align__(16) __half Ks[64 * KPITCH];   // K chunk; aliased as P
    __shared__ __align__(16) __half Vs[64 * KPITCH];

    const int tid  = threadIdx.x;
    const int lane = tid & 31;
    const int w    = tid >> 5;
    const int g    = lane >> 2;
    const int qq   = lane & 3;
    const int b    = blockIdx.z;
    const int h    = blockIdx.y;
    const int q0   = blockIdx.x * 64;
    const int kvh  = h / NG_;
    const int mrow = w * 16;

    const __half* Qbase = Q  + ((((size_t)b * H_ + h) * S_) + q0) * DH_;
    const __half* Kbase = Kb + (((size_t)b * KVH_ + kvh) * S_) * DH_;
    const __half* Vbase = Vb + (((size_t)b * KVH_ + kvh) * S_) * DH_;

    const uint32_t sK = smem_u32(Ks);
    const uint32_t sV = smem_u32(Vs);

    // ldmatrix lane offsets
    const int aRow = (lane & 7) + 8 * ((lane >> 3) & 1);   // + mrow (A frags: Q/P)
    const int aCol = 8 * (lane >> 4);                      // + kk*16
    const int bRowK = (lane & 7) + 8 * (lane >> 4);        // K non-trans: key row (+np*16)
    const int bColK = 8 * ((lane >> 3) & 1);               // + kk*16
    const int bRowV = (lane & 7) + 8 * ((lane >> 3) & 1);  // V trans: k row (+kk*16)
    const int bColV = 8 * (lane >> 4);                     // + np*16

    // stage Q tile through Ks, pull A-frags into registers
    for (int it = 0; it < 4; ++it) {
        int i = it * 128 + tid;
        int r = i >> 3, c = (i & 7) * 8;
        *(uint4*)(&Ks[r * KPITCH + c]) = *(const uint4*)(&Qbase[(size_t)r * DH_ + c]);
    }
    __syncthreads();
    uint32_t qf[4][4];
#pragma unroll
    for (int kk = 0; kk < 4; ++kk) {
        uint32_t addr = sK + (uint32_t)((mrow + aRow) * KPITCH + kk * 16 + aCol) * 2;
        LDMX4(qf[kk], addr);
    }

    float o[8][4];
#pragma unroll
    for (int nf = 0; nf < 8; ++nf)
#pragma unroll
        for (int j = 0; j < 4; ++j) o[nf][j] = 0.f;
    float m0 = -INFINITY, m1 = -INFINITY, l0 = 0.f, l1 = 0.f;

    const int row0 = q0 + mrow + g;
    const int row1 = row0 + 8;

    int q_lo = q0 - (WINDOW_ - 1); if (q_lo < 0) q_lo = 0;
    const int c_lo = q_lo >> 6;
    const int c_hi = q0 >> 6;
    const int nch  = c_hi - c_lo + 1 + (c_lo > 0 ? 1 : 0);

    for (int it = 0; it < nch; ++it) {
        const int c = (c_lo > 0) ? (it == 0 ? 0 : c_lo + it - 1) : (c_lo + it);

        __syncthreads();   // previous chunk fully consumed
        for (int p = 0; p < 4; ++p) {
            int i = p * 128 + tid;
            int r = i >> 3, cc = (i & 7) * 8;
            *(uint4*)(&Ks[r * KPITCH + cc]) =
                *(const uint4*)(&Kbase[((size_t)(c * 64 + r)) * DH_ + cc]);
            *(uint4*)(&Vs[r * KPITCH + cc]) =
                *(const uint4*)(&Vbase[((size_t)(c * 64 + r)) * DH_ + cc]);
        }
        __syncthreads();

        // ---- S = Q K^T ----
        float s[8][4];
#pragma unroll
        for (int nf = 0; nf < 8; ++nf)
#pragma unroll
            for (int j = 0; j < 4; ++j) s[nf][j] = 0.f;

#pragma unroll
        for (int kk = 0; kk < 4; ++kk) {
#pragma unroll
            for (int np = 0; np < 4; ++np) {
                uint32_t bf[4];
                uint32_t addr = sK + (uint32_t)((np * 16 + bRowK) * KPITCH +
                                                kk * 16 + bColK) * 2;
                LDMX4(bf, addr);
                MMA_F16(s[np * 2],     qf[kk], (&bf[0]));
                MMA_F16(s[np * 2 + 1], qf[kk], (&bf[2]));
            }
        }

        // ---- softcap + mask + row max ----
        float rmax0 = -INFINITY, rmax1 = -INFINITY;
#pragma unroll
        for (int nf = 0; nf < 8; ++nf) {
            const int kc0 = c * 64 + nf * 8 + 2 * qq;
            const int kc1 = kc0 + 1;
#pragma unroll
            for (int j = 0; j < 4; ++j) {
                const int kc = (j & 1) ? kc1 : kc0;
                const int qr = (j < 2) ? row0 : row1;
                float x = s[nf][j] * ATTN_SCALE_;
                float e = __expf(x * (2.0f / 15.0f));
                x = 15.0f * ((e - 1.0f) / (e + 1.0f));
                bool valid = (kc <= qr) && ((kc + WINDOW_ > qr) || (kc < NGLOBAL_));
                x = valid ? x : -INFINITY;
                s[nf][j] = x;
                if (j < 2) rmax0 = fmaxf(rmax0, x); else rmax1 = fmaxf(rmax1, x);
            }
        }
        rmax0 = fmaxf(rmax0, __shfl_xor_sync(0xffffffffu, rmax0, 1));
        rmax0 = fmaxf(rmax0, __shfl_xor_sync(0xffffffffu, rmax0, 2));
        rmax1 = fmaxf(rmax1, __shfl_xor_sync(0xffffffffu, rmax1, 1));
        rmax1 = fmaxf(rmax1, __shfl_xor_sync(0xffffffffu, rmax1, 2));

        const float mn0 = fmaxf(fmaxf(m0, rmax0), -1e30f);
        const float mn1 = fmaxf(fmaxf(m1, rmax1), -1e30f);
        const float a0 = __expf(m0 - mn0);
        const float a1 = __expf(m1 - mn1);

        float rs0 = 0.f, rs1 = 0.f;
#pragma unroll
        for (int nf = 0; nf < 8; ++nf) {
            float p0 = __expf(s[nf][0] - mn0);
            float p1 = __expf(s[nf][1] - mn0);
            float p2 = __expf(s[nf][2] - mn1);
            float p3 = __expf(s[nf][3] - mn1);
            rs0 += p0 + p1; rs1 += p2 + p3;
            s[nf][0] = p0; s[nf][1] = p1; s[nf][2] = p2; s[nf][3] = p3;
        }
        rs0 += __shfl_xor_sync(0xffffffffu, rs0, 1);
        rs0 += __shfl_xor_sync(0xffffffffu, rs0, 2);
        rs1 += __shfl_xor_sync(0xffffffffu, rs1, 1);
        rs1 += __shfl_xor_sync(0xffffffffu, rs1, 2);
        l0 = l0 * a0 + rs0;
        l1 = l1 * a1 + rs1;
#pragma unroll
        for (int nf = 0; nf < 8; ++nf) {
            o[nf][0] *= a0; o[nf][1] *= a0;
            o[nf][2] *= a1; o[nf][3] *= a1;
        }
        m0 = mn0; m1 = mn1;

        __syncthreads();   // all warps done reading Ks -> reuse as P buffer

        // ---- store P (fp16) into Ks region ----
#pragma unroll
        for (int nf = 0; nf < 8; ++nf) {
            const int col = nf * 8 + 2 * qq;
            *(__half2*)(&Ks[(mrow + g)     * KPITCH + col]) = __floats2half2_rn(s[nf][0], s[nf][1]);
            *(__half2*)(&Ks[(mrow + g + 8) * KPITCH + col]) = __floats2half2_rn(s[nf][2], s[nf][3]);
        }
        __syncwarp();      // each warp reads only its own 16 P rows

        // ---- O += P V ----
#pragma unroll
        for (int kk = 0; kk < 4; ++kk) {
            uint32_t af[4];
            uint32_t aaddr = sK + (uint32_t)((mrow + aRow) * KPITCH + kk * 16 + aCol) * 2;
            LDMX4(af, aaddr);
#pragma unroll
            for (int np = 0; np < 4; ++np) {
                uint32_t bf[4];
                uint32_t addr = sV + (uint32_t)((kk * 16 + bRowV) * KPITCH +
                                                np * 16 + bColV) * 2;
                LDMX4T(bf, addr);
                MMA_F16(o[np * 2],     af, (&bf[0]));
                MMA_F16(o[np * 2 + 1], af, (&bf[2]));
            }
        }
    }

    // ---- epilogue: normalize, write fp16 ctx[b][s][h][d] ----
    const float inv0 = 1.0f / l0;
    const float inv1 = 1.0f / l1;
    __half* c0p = ctx + ((((size_t)b * S_ + row0) * H_) + h) * DH_;
    __half* c1p = ctx + ((((size_t)b * S_ + row1) * H_) + h) * DH_;
#pragma unroll
    for (int nf = 0; nf < 8; ++nf) {
        const int d = nf * 8 + 2 * qq;
        *(__half2*)(&c0p[d]) = __floats2half2_rn(o[nf][0] * inv0, o[nf][1] * inv0);
        *(__half2*)(&c1p[d]) = __floats2half2_rn(o[nf][2] * inv1, o[nf][3] * inv1);
    }
}

// ---------------------------------------------------------------------------
// Launch
// ---------------------------------------------------------------------------
extern "C" void kernel_launch(void* const* d_in, const int* in_sizes, int n_in,
                              void* d_out, int out_size)
{
    const float* x    = (const float*)d_in[0];
    const float* cosb = (const float*)d_in[1];
    const float* sinb = (const float*)d_in[2];
    // d_in[3] = mask (pure causal) — computed analytically, unused
    const float* Wq   = (const float*)d_in[4];
    const float* Wk   = (const float*)d_in[5];
    const float* Wv   = (const float*)d_in[6];
    const float* Wo   = (const float*)d_in[7];
    float* out        = (float*)d_out;

    __half *x16, *wq16, *wk16, *wv16, *wo16, *q16, *k16, *v16, *ctx16;
    cudaGetSymbolAddress((void**)&x16,   g_x16);
    cudaGetSymbolAddress((void**)&wq16,  g_wq16);
    cudaGetSymbolAddress((void**)&wk16,  g_wk16);
    cudaGetSymbolAddress((void**)&wv16,  g_wv16);
    cudaGetSymbolAddress((void**)&wo16,  g_wo16);
    cudaGetSymbolAddress((void**)&q16,   g_q16);
    cudaGetSymbolAddress((void**)&k16,   g_k16);
    cudaGetSymbolAddress((void**)&v16,   g_v16);
    cudaGetSymbolAddress((void**)&ctx16, g_ctx16);

    // fp16 conversions
    cvt_half_kernel<<<2048, 256>>>(x, x16, (M_TOT * DM_) / 4);
    cvt_weights_kernel<<<1280, 256>>>(Wq, Wk, Wv, Wo, wq16, wk16, wv16, wo16);

    // Fused QKV projections (fp16 tensor cores), scatter to [b,h,s,d] fp16
    h16_gemm<<<dim3(12, M_TOT / 128), 256>>>(x16, wq16, wk16, wv16, q16, k16, v16, 0);

    // L2-norm + RoPE (q and k, fp16 in-place, single launch)
    norm_rope16_kernel<<<(NQROWS + NKROWS) / 8, 256>>>(q16, k16, cosb, sinb);

    // Flash attention (fp16 mma)
    attn_h16_kernel<<<dim3(S_ / 64, H_, B_), dim3(128)>>>(q16, k16, v16, ctx16);

    // Output projection (fp16 mma, fp32 row-major into d_out)
    h16_gemm<<<dim3(8, M_TOT / 128), 256>>>(ctx16, wo16, nullptr, nullptr,
                                            out, nullptr, nullptr, 1);
}